// round 15
// baseline (speedup 1.0000x reference)
#include <cuda_runtime.h>
#include <cstdint>

#define T_STEPS 12
#define BATCH   64
#define NODE    207
#define HID     16
#define HDIM    6624          // NODE*HID*2
#define IN_DIM  16560         // NODE*HID*5
#define X_DIM   3312          // NODE*HID
#define NBLK    138           // column blocks: 138 * 48 cols = 6624
#define CPB     48            // cols per block
#define RPAD    6720          // rows padded to 14*480
#define NPASS   14            // 480-row passes
#define PROWS   480
#define SLABF4  80640         // f4 per slab: 14*12*480
#define NG      (T_STEPS * BATCH)   // 768 global steps
// g_sync layout: [0]=bar cnt, [1]=bar phase, [2 .. 2+NG*138) counters,
//                [2+NG*138 .. 2+2*NG*138) flags
#define SYNC_WORDS (2 + 2 * NG * NBLK)

// Scratch (device globals: allocation-free rule)
__device__ float    g_hz[BATCH * HDIM];
__device__ float    g_inpT[IN_DIM * BATCH];
__device__ float    g_pre[BATCH * HDIM];
__device__ float    g_acc[BATCH * RPAD];            // per-step accumulators
__device__ float4   g_slab[(size_t)NBLK * SLABF4];  // permuted column slabs (~178 MB)
__device__ unsigned g_sync[SYNC_WORDS];

// ---------------------------------------------------------------------------
// Kernel H: build permuted column slabs.
// slab[p] f4 index (pass*12 + j)*480 + tr  <-  W[pass*480+tr][48p+4j .. +4)
// ---------------------------------------------------------------------------
__global__ __launch_bounds__(256) void kH(const float* __restrict__ W)
{
    const int p    = blockIdx.x / NPASS;
    const int pass = blockIdx.x % NPASS;
    float4* slab = g_slab + (size_t)p * SLABF4 + (size_t)pass * 12 * PROWS;

    for (int i = threadIdx.x; i < 12 * PROWS; i += 256) {
        const int j  = i / PROWS;
        const int tr = i % PROWS;
        const int row = pass * PROWS + tr;
        float4 v = make_float4(0.f, 0.f, 0.f, 0.f);
        if (row < HDIM)
            v = *reinterpret_cast<const float4*>(
                W + (size_t)row * HDIM + p * CPB + j * 4);
        slab[(size_t)j * PROWS + tr] = v;
    }
}

// ---------------------------------------------------------------------------
// Kernel A: build inpT[:, b] directly (transposed layout).
// ---------------------------------------------------------------------------
__global__ __launch_bounds__(256) void kA(
    const float* __restrict__ hz, const float* __restrict__ sv_t,
    const float* __restrict__ Wf, const float* __restrict__ bf,
    const float* __restrict__ Wg, const float* __restrict__ bg,
    const float* __restrict__ conv_w, float* __restrict__ inpT)
{
    const int blk = blockIdx.x;
    const int b = blk / NODE;
    const int n = blk % NODE;
    const int tid = threadIdx.x;

    __shared__ float sh[HID], sz[HID], sf[HID * 2], sg[HID * HID];

    if (tid < 32) {
        float v = hz[b * HDIM + n * 32 + tid];
        if (tid & 1) sz[tid >> 1] = v;
        else         sh[tid >> 1] = v;
    }
    __syncthreads();

    {
        float acc = bg[tid];
#pragma unroll
        for (int l = 0; l < HID; l++) acc += sz[l] * Wg[l * 256 + tid];
        sg[tid] = tanhf(acc);
    }
    if (tid < 32) {
        float acc = bf[tid];
#pragma unroll
        for (int i = 0; i < HID; i++) acc += sh[i] * Wf[i * 32 + tid];
        sf[tid] = tanhf(acc);
    }
    __syncthreads();

    if (tid < 32) {
        const int i = tid >> 1, c = tid & 1;
        float acc = 0.f;
#pragma unroll
        for (int j = 0; j < HID; j++) acc += sg[i * HID + j] * sf[j * 2 + c];
        const int base = X_DIM + n * 64 + i * 4 + c * 2;
        inpT[(size_t)base * BATCH + b]       = sf[i * 2 + c];
        inpT[(size_t)(base + 1) * BATCH + b] = acc;
    }
    if (tid < HID) {
        float v = sv_t[(b * NODE + n) * 2 + 1];
        inpT[(size_t)(tid * NODE + n) * BATCH + b] = conv_w[tid] * v;
    }
}

// ---------------------------------------------------------------------------
// Kernel B: pre = inp @ W_ih^T + b_ih (Wih streamed evict-first)
// ---------------------------------------------------------------------------
__global__ __launch_bounds__(256) void kB(
    const float* __restrict__ inpT, const float* __restrict__ Wih,
    const float* __restrict__ bih, float* __restrict__ pre)
{
    const int tid = threadIdx.x;
    const int b  = tid & 63;
    const int jg = tid >> 6;
    const int o0 = blockIdx.x * 16 + jg * 4;

    const float* w0 = Wih + (size_t)o0 * IN_DIM;

    float acc[4];
#pragma unroll
    for (int k = 0; k < 4; k++) acc[k] = 0.f;

    for (int i = 0; i < IN_DIM; i += 4) {
        const float x0 = inpT[(size_t)(i    ) * BATCH + b];
        const float x1 = inpT[(size_t)(i + 1) * BATCH + b];
        const float x2 = inpT[(size_t)(i + 2) * BATCH + b];
        const float x3 = inpT[(size_t)(i + 3) * BATCH + b];
#pragma unroll
        for (int k = 0; k < 4; k++) {
            const float4 w = __ldcs(reinterpret_cast<const float4*>(
                                        w0 + (size_t)k * IN_DIM + i));
            acc[k] += w.x * x0 + w.y * x1 + w.z * x2 + w.w * x3;
        }
    }
#pragma unroll
    for (int k = 0; k < 4; k++)
        pre[b * HDIM + o0 + k] = acc[k] + bih[o0 + k];
}

// ---------------------------------------------------------------------------
// Kernel C (persistent DATAFLOW, no per-step grid barrier):
// 138 blocks x 512 threads, 1 CTA/SM. Block p owns cols [48p,48p+48).
// Per step s: needs only h_{s-1}[48p..48p+48) (flag-gated), then 14 passes
// of 480 rows: y[row] += slab . h, atomicAdd into acc[s] (pre-initialized
// to pre+bhh). Per-48-row-range counters; last arriver finalizes (tanh) and
// sets the flag. One grid barrier per launch (after acc init).
// ---------------------------------------------------------------------------
__global__ __launch_bounds__(512, 1) void kC_persist(
    const float4* __restrict__ slab4, float* __restrict__ acc,
    const float* __restrict__ pre, const float* __restrict__ bhh,
    float* __restrict__ hz, unsigned* __restrict__ sync, int t)
{
    __shared__ float4 s_h4[12];
    __shared__ int s_final[12];
    __shared__ int s_nf;
    const int tid = threadIdx.x;
    const int p = blockIdx.x;

    unsigned* cnt  = sync + 2;
    unsigned* flag = sync + 2 + (size_t)NG * NBLK;

    // ---- init: acc[s][own rows] = pre + bhh (s>=1); h_0 = tanh(pre0+bhh) ----
    const int r0 = p * CPB;
    const int rcnt = (p == NBLK - 1) ? (RPAD - r0) : CPB;   // last block covers pad
    for (int i = tid; i < rcnt * BATCH; i += 512) {
        const int s = i / rcnt;
        const int row = r0 + (i % rcnt);
        if (s == 0) {
            if (row < HDIM)
                __stcg(&hz[row], tanhf(pre[row] + bhh[row]));
        } else {
            const float v = (row < HDIM)
                ? (pre[(size_t)s * HDIM + row] + bhh[row]) : 0.f;
            __stcg(&acc[(size_t)s * RPAD + row], v);
        }
    }
    __threadfence();
    __syncthreads();
    if (tid == 0) {       // one grid barrier per launch, monotone index t+1
        const unsigned k = (unsigned)(t + 1);
        const unsigned old = atomicAdd(&sync[0], 1u);
        if (old == k * NBLK - 1u) {
            atomicExch(&sync[1], k);
        } else {
            volatile unsigned* ph = &sync[1];
            while (*ph < k) __nanosleep(64);
        }
    }
    __syncthreads();

    for (int s = 1; s < BATCH; s++) {
        const int g = t * BATCH + s;

        // wait for own 48 inputs (h_{s-1}[48p..)); s==1 inputs self-written
        if (s >= 2) {
            if (tid == 0) {
                volatile unsigned* f = &flag[(size_t)(g - 1) * NBLK + p];
                while (*f == 0u) __nanosleep(32);
            }
            __syncthreads();
        }
        if (tid < 12)
            s_h4[tid] = __ldcg(reinterpret_cast<const float4*>(
                                   hz + (size_t)(s - 1) * HDIM) + p * 12 + tid);
        __syncthreads();
        float4 hv[12];
#pragma unroll
        for (int j = 0; j < 12; j++) hv[j] = s_h4[j];

        // 14 passes, ring offset to decorrelate RED bursts
        for (int jj = 0; jj < NPASS; jj++) {
            const int pass = (p + jj) % NPASS;
            if (tid < PROWS) {
                const float4* base = slab4 + (size_t)p * SLABF4
                                   + (size_t)pass * 12 * PROWS;
                float y = 0.f;
                float4 w[6];
#pragma unroll
                for (int j = 0; j < 6; j++) w[j] = __ldcs(&base[j * PROWS + tid]);
#pragma unroll
                for (int j = 0; j < 6; j++)
                    y += w[j].x*hv[j].x + w[j].y*hv[j].y
                       + w[j].z*hv[j].z + w[j].w*hv[j].w;
#pragma unroll
                for (int j = 0; j < 6; j++) w[j] = __ldcs(&base[(6 + j) * PROWS + tid]);
#pragma unroll
                for (int j = 0; j < 6; j++)
                    y += w[j].x*hv[6+j].x + w[j].y*hv[6+j].y
                       + w[j].z*hv[6+j].z + w[j].w*hv[6+j].w;
                atomicAdd(&acc[(size_t)s * RPAD + pass * PROWS + tid], y);
            }
            __threadfence();
            if (tid == 0) s_nf = 0;
            __syncthreads();

            const int nr = (pass == NPASS - 1) ? 8 : 10;   // valid 48-row ranges
            if (tid < nr) {
                const int q = pass * 10 + tid;
                const unsigned old = atomicAdd(&cnt[(size_t)g * NBLK + q], 1u);
                if (old == (unsigned)(NBLK - 1)) {
                    const int k2 = atomicAdd(&s_nf, 1);
                    s_final[k2] = q;
                }
            }
            __syncthreads();
            const int nf = s_nf;
            for (int i = 0; i < nf; i++) {
                const int q = s_final[i];
                if (tid < CPB) {
                    const int row = q * CPB + tid;
                    __stcg(&hz[(size_t)s * HDIM + row],
                           tanhf(__ldcg(&acc[(size_t)s * RPAD + row])));
                }
                __threadfence();
                __syncthreads();
                if (tid == 0) atomicExch(&flag[(size_t)g * NBLK + q], 1u);
            }
            if (nf) __syncthreads();
        }
    }
}

// ---------------------------------------------------------------------------
extern "C" void kernel_launch(void* const* d_in, const int* in_sizes, int n_in,
                              void* d_out, int out_size)
{
    const float* sv    = (const float*)d_in[0];
    const float* init0 = (const float*)d_in[1];
    const float* Wf    = (const float*)d_in[2];
    const float* bf    = (const float*)d_in[3];
    const float* Wg    = (const float*)d_in[4];
    const float* bg    = (const float*)d_in[5];
    const float* cw    = (const float*)d_in[6];
    const float* Wih   = (const float*)d_in[7];
    const float* bih   = (const float*)d_in[8];
    const float* Whh   = (const float*)d_in[9];
    const float* bhh   = (const float*)d_in[10];

    float *hz, *inpT, *pre, *acc;
    float4* slab;
    unsigned* sync;
    cudaGetSymbolAddress((void**)&hz,   g_hz);
    cudaGetSymbolAddress((void**)&inpT, g_inpT);
    cudaGetSymbolAddress((void**)&pre,  g_pre);
    cudaGetSymbolAddress((void**)&acc,  g_acc);
    cudaGetSymbolAddress((void**)&slab, g_slab);
    cudaGetSymbolAddress((void**)&sync, g_sync);

    // Launch order: memset, kH, memcpy, kA, kB, kC -> kC is profiled op #5
    cudaMemsetAsync(sync, 0, (size_t)SYNC_WORDS * sizeof(unsigned));
    kH<<<NBLK * NPASS, 256>>>(Whh);
    cudaMemcpyAsync(hz, init0, (size_t)BATCH * HDIM * sizeof(float),
                    cudaMemcpyDeviceToDevice);

    for (int t = 0; t < T_STEPS; t++) {
        kA<<<BATCH * NODE, 256>>>(hz, sv + (size_t)t * BATCH * NODE * 2,
                                  Wf, bf, Wg, bg, cw, inpT);
        kB<<<HDIM / 16, 256>>>(inpT, Wih, bih, pre);
        kC_persist<<<NBLK, 512>>>(slab, acc, pre, bhh, hz, sync, t);
    }

    cudaMemcpyAsync(d_out, hz, (size_t)BATCH * HDIM * sizeof(float),
                    cudaMemcpyDeviceToDevice);
}

// round 16
// speedup vs baseline: 1.6204x; 1.6204x over previous
#include <cuda_runtime.h>
#include <cstdint>

#define T_STEPS 12
#define BATCH   64
#define NODE    207
#define HID     16
#define HDIM    6624          // NODE*HID*2
#define IN_DIM  16560         // NODE*HID*5
#define X_DIM   3312          // NODE*HID
#define WSTRIDE 6656          // padded row stride (1664 float4)
#define NB      414           // persistent grid, 3 CTAs/SM
#define NG      (T_STEPS * BATCH)
#define SMEM_BYTES (WSTRIDE * 4)   // 26.6 KB (h staging) -> 3 CTAs/SM
// g_sync: [0]=bar count, [1]=bar phase, [2 .. 2+NG) = per-step row counters

// Scratch (device globals: allocation-free rule)
__device__ float    g_hz[BATCH * HDIM];
__device__ float    g_inpT[IN_DIM * BATCH];
__device__ float    g_pre[BATCH * HDIM];
__device__ float    g_w[(size_t)HDIM * WSTRIDE];    // padded fp32 W_hh (~176 MB)
__device__ unsigned g_sync[2 + NG];

// ---------------------------------------------------------------------------
__global__ __launch_bounds__(256) void kH(const float* __restrict__ W)
{
    const int o = blockIdx.x;
    for (int i = threadIdx.x; i < WSTRIDE; i += 256)
        g_w[(size_t)o * WSTRIDE + i] = (i < HDIM) ? W[(size_t)o * HDIM + i] : 0.f;
}

// ---------------------------------------------------------------------------
// Kernel A: build inpT[:, b] directly (transposed layout).
// ---------------------------------------------------------------------------
__global__ __launch_bounds__(256) void kA(
    const float* __restrict__ hz, const float* __restrict__ sv_t,
    const float* __restrict__ Wf, const float* __restrict__ bf,
    const float* __restrict__ Wg, const float* __restrict__ bg,
    const float* __restrict__ conv_w, float* __restrict__ inpT)
{
    const int blk = blockIdx.x;
    const int b = blk / NODE;
    const int n = blk % NODE;
    const int tid = threadIdx.x;

    __shared__ float sh[HID], sz[HID], sf[HID * 2], sg[HID * HID];

    if (tid < 32) {
        float v = hz[b * HDIM + n * 32 + tid];
        if (tid & 1) sz[tid >> 1] = v;
        else         sh[tid >> 1] = v;
    }
    __syncthreads();

    {
        float acc = bg[tid];
#pragma unroll
        for (int l = 0; l < HID; l++) acc += sz[l] * Wg[l * 256 + tid];
        sg[tid] = tanhf(acc);
    }
    if (tid < 32) {
        float acc = bf[tid];
#pragma unroll
        for (int i = 0; i < HID; i++) acc += sh[i] * Wf[i * 32 + tid];
        sf[tid] = tanhf(acc);
    }
    __syncthreads();

    if (tid < 32) {
        const int i = tid >> 1, c = tid & 1;
        float acc = 0.f;
#pragma unroll
        for (int j = 0; j < HID; j++) acc += sg[i * HID + j] * sf[j * 2 + c];
        const int base = X_DIM + n * 64 + i * 4 + c * 2;
        inpT[(size_t)base * BATCH + b]       = sf[i * 2 + c];
        inpT[(size_t)(base + 1) * BATCH + b] = acc;
    }
    if (tid < HID) {
        float v = sv_t[(b * NODE + n) * 2 + 1];
        inpT[(size_t)(tid * NODE + n) * BATCH + b] = conv_w[tid] * v;
    }
}

// ---------------------------------------------------------------------------
// Kernel B: pre = inp @ W_ih^T + b_ih (Wih streamed evict-first)
// ---------------------------------------------------------------------------
__global__ __launch_bounds__(256) void kB(
    const float* __restrict__ inpT, const float* __restrict__ Wih,
    const float* __restrict__ bih, float* __restrict__ pre)
{
    const int tid = threadIdx.x;
    const int b  = tid & 63;
    const int jg = tid >> 6;
    const int o0 = blockIdx.x * 16 + jg * 4;

    const float* w0 = Wih + (size_t)o0 * IN_DIM;

    float acc[4];
#pragma unroll
    for (int k = 0; k < 4; k++) acc[k] = 0.f;

    for (int i = 0; i < IN_DIM; i += 4) {
        const float x0 = inpT[(size_t)(i    ) * BATCH + b];
        const float x1 = inpT[(size_t)(i + 1) * BATCH + b];
        const float x2 = inpT[(size_t)(i + 2) * BATCH + b];
        const float x3 = inpT[(size_t)(i + 3) * BATCH + b];
#pragma unroll
        for (int k = 0; k < 4; k++) {
            const float4 w = __ldcs(reinterpret_cast<const float4*>(
                                        w0 + (size_t)k * IN_DIM + i));
            acc[k] += w.x * x0 + w.y * x1 + w.z * x2 + w.w * x3;
        }
    }
#pragma unroll
    for (int k = 0; k < 4; k++)
        pre[b * HDIM + o0 + k] = acc[k] + bih[o0 + k];
}

// ---------------------------------------------------------------------------
// Kernel C (persistent, fp32 streaming + 1-ROW WARP STEALING):
// 414 blocks x 256 threads, 3 CTAs/SM (24 warps/SM).
// Per step: stage h to smem, then each warp steals single rows via the
// per-step counter (6624 chunks vs 3312 warps -> 2x ratio; straggler tail
// = one row sweep). Plain float4 __ldcs streaming, x4 unroll.
// ---------------------------------------------------------------------------
extern __shared__ float s_dyn[];

__global__ __launch_bounds__(256, 3) void kC_persist(
    const float* __restrict__ W, const float* __restrict__ pre,
    const float* __restrict__ bhh, float* __restrict__ hz, int t)
{
    float* sh = s_dyn;                 // [0, WSTRIDE) floats
    const int tid  = threadIdx.x;
    const int lane = tid & 31;
    const float4* H4 = reinterpret_cast<const float4*>(sh);

    if (tid < WSTRIDE - HDIM) sh[HDIM + tid] = 0.f;   // zero smem h pad

    for (int step = 0; step < BATCH; step++) {
        const int idx = t * BATCH + step;
        const float* pre_b = pre + (size_t)step * HDIM;
        float* hout = hz + (size_t)step * HDIM;

        if (step > 0) {
            __syncthreads();          // WAR: previous step's smem readers done
            const float4* hp4 = reinterpret_cast<const float4*>(
                hz + (size_t)(step - 1) * HDIM);
            for (int i = tid; i < HDIM / 4; i += 256)
                reinterpret_cast<float4*>(sh)[i] = __ldcg(&hp4[i]);
            __syncthreads();

            // warp-level single-row stealing
            for (;;) {
                int row;
                if (lane == 0) row = (int)atomicAdd(&g_sync[2 + idx], 1u);
                row = __shfl_sync(0xffffffffu, row, 0);
                if (row >= HDIM) break;

                const float4* W0 = reinterpret_cast<const float4*>(
                    W + (size_t)row * WSTRIDE);

                float a = 0.f;
#pragma unroll 1
                for (int c = 0; c < 52; c += 4) {
                    float4 w0 = __ldcs(&W0[(c    ) * 32 + lane]);
                    float4 w1 = __ldcs(&W0[(c + 1) * 32 + lane]);
                    float4 w2 = __ldcs(&W0[(c + 2) * 32 + lane]);
                    float4 w3 = __ldcs(&W0[(c + 3) * 32 + lane]);
                    const float4 h0 = H4[(c    ) * 32 + lane];
                    const float4 h1 = H4[(c + 1) * 32 + lane];
                    const float4 h2 = H4[(c + 2) * 32 + lane];
                    const float4 h3 = H4[(c + 3) * 32 + lane];
                    a += w0.x*h0.x + w0.y*h0.y + w0.z*h0.z + w0.w*h0.w;
                    a += w1.x*h1.x + w1.y*h1.y + w1.z*h1.z + w1.w*h1.w;
                    a += w2.x*h2.x + w2.y*h2.y + w2.z*h2.z + w2.w*h2.w;
                    a += w3.x*h3.x + w3.y*h3.y + w3.z*h3.z + w3.w*h3.w;
                }
#pragma unroll
                for (int s = 16; s; s >>= 1)
                    a += __shfl_xor_sync(0xffffffffu, a, s);
                if (lane == 0)
                    __stcg(hout + row, tanhf(a + pre_b[row] + bhh[row]));
            }
        } else {
            // step 0: h_prev = 0
            for (int o = blockIdx.x * 256 + tid; o < HDIM; o += NB * 256)
                __stcg(hout + o, tanhf(pre_b[o] + bhh[o]));
        }

        // grid barrier
        __threadfence();
        __syncthreads();
        if (tid == 0) {
            const unsigned k = (unsigned)(t * BATCH + step + 1);
            const unsigned old = atomicAdd(&g_sync[0], 1u);
            if (old == k * NB - 1u) {
                atomicExch(&g_sync[1], k);
            } else {
                volatile unsigned* ph = &g_sync[1];
                while (*ph < k) __nanosleep(64);
            }
        }
        __syncthreads();
    }
}

// ---------------------------------------------------------------------------
extern "C" void kernel_launch(void* const* d_in, const int* in_sizes, int n_in,
                              void* d_out, int out_size)
{
    const float* sv    = (const float*)d_in[0];
    const float* init0 = (const float*)d_in[1];
    const float* Wf    = (const float*)d_in[2];
    const float* bf    = (const float*)d_in[3];
    const float* Wg    = (const float*)d_in[4];
    const float* bg    = (const float*)d_in[5];
    const float* cw    = (const float*)d_in[6];
    const float* Wih   = (const float*)d_in[7];
    const float* bih   = (const float*)d_in[8];
    const float* Whh   = (const float*)d_in[9];
    const float* bhh   = (const float*)d_in[10];

    float *hz, *inpT, *pre, *wpad;
    unsigned* sync;
    cudaGetSymbolAddress((void**)&hz,   g_hz);
    cudaGetSymbolAddress((void**)&inpT, g_inpT);
    cudaGetSymbolAddress((void**)&pre,  g_pre);
    cudaGetSymbolAddress((void**)&wpad, g_w);
    cudaGetSymbolAddress((void**)&sync, g_sync);

    static int smem_set = 0;
    if (!smem_set) {
        cudaFuncSetAttribute(kC_persist,
                             cudaFuncAttributeMaxDynamicSharedMemorySize,
                             SMEM_BYTES);
        smem_set = 1;
    }

    // Launch order: memset, kH, memcpy, kA, kB, kC -> kC is profiled op #5
    cudaMemsetAsync(sync, 0, (2 + NG) * sizeof(unsigned));
    kH<<<HDIM, 256>>>(Whh);
    cudaMemcpyAsync(hz, init0, (size_t)BATCH * HDIM * sizeof(float),
                    cudaMemcpyDeviceToDevice);

    for (int t = 0; t < T_STEPS; t++) {
        kA<<<BATCH * NODE, 256>>>(hz, sv + (size_t)t * BATCH * NODE * 2,
                                  Wf, bf, Wg, bg, cw, inpT);
        kB<<<HDIM / 16, 256>>>(inpT, Wih, bih, pre);
        kC_persist<<<NB, 256, SMEM_BYTES>>>(wpad, pre, bhh, hz, t);
    }

    cudaMemcpyAsync(d_out, hz, (size_t)BATCH * HDIM * sizeof(float),
                    cudaMemcpyDeviceToDevice);
}